// round 9
// baseline (speedup 1.0000x reference)
#include <cuda_runtime.h>
#include <cuda_bf16.h>

// Composed chain outputs (written by compose_kernel):
//   g_Bhi/g_Blo: bf16 split of M^T laid out [16][792] (n-major, k-contiguous,
//                row stride 792 bf16; rows 10..15 and cols 784..791 zero)
//   g_c: folded bias [10]
__device__ __align__(16) __nv_bfloat16 g_Bhi[16 * 792];
__device__ __align__(16) __nv_bfloat16 g_Blo[16 * 792];
__device__ float g_c[10];

// ---------------------------------------------------------------------------
// Compose kernel (grid=8): P = W8*...*W1 via thread-local register chain
// (70 threads, no syncs), then M = P*W0 slice per block, split into bf16
// hi/lo and written into the padded B layout. Block 0 folds bias, block 7
// zeroes the padding regions.
// ---------------------------------------------------------------------------
__global__ void __launch_bounds__(256) compose_kernel(
    const float* __restrict__ W0, const float* __restrict__ b0,
    const float* __restrict__ W1, const float* __restrict__ b1,
    const float* __restrict__ W2, const float* __restrict__ b2,
    const float* __restrict__ W3, const float* __restrict__ b3,
    const float* __restrict__ W4, const float* __restrict__ b4,
    const float* __restrict__ W5, const float* __restrict__ b5,
    const float* __restrict__ W6, const float* __restrict__ b6,
    const float* __restrict__ W7, const float* __restrict__ b7,
    const float* __restrict__ W8, const float* __restrict__ b8)
{
    __shared__ float sW2[10 * 31];
    __shared__ float sWs[6][100];
    __shared__ float sb1[31];
    __shared__ float sbs[7][10];
    __shared__ float sb0[69];
    __shared__ float sP[10 * 69];
    __shared__ float sc[10];

    const int tid = threadIdx.x;

    for (int e = tid; e < 310; e += 256) sW2[e] = W2[e];
    if (tid < 100) {
        sWs[0][tid] = W3[tid]; sWs[1][tid] = W4[tid]; sWs[2][tid] = W5[tid];
        sWs[3][tid] = W6[tid]; sWs[4][tid] = W7[tid]; sWs[5][tid] = W8[tid];
    }
    if (tid < 31) sb1[tid] = b1[tid];
    if (tid < 69) sb0[tid] = b0[tid];
    if (tid < 10) {
        sbs[0][tid] = b2[tid]; sbs[1][tid] = b3[tid]; sbs[2][tid] = b4[tid];
        sbs[3][tid] = b5[tid]; sbs[4][tid] = b6[tid]; sbs[5][tid] = b7[tid];
        sbs[6][tid] = b8[tid];
    }
    __syncthreads();

    if (tid < 70) {
        const bool isBias = (tid == 69);
        float a[31];
        if (!isBias) {
            #pragma unroll
            for (int m = 0; m < 31; m++) a[m] = W1[m * 69 + tid];
        } else {
            #pragma unroll
            for (int m = 0; m < 31; m++) a[m] = sb1[m];
        }
        float t[10];
        #pragma unroll
        for (int j = 0; j < 10; j++) {
            float s = isBias ? sbs[0][j] : 0.f;
            #pragma unroll
            for (int m = 0; m < 31; m++) s += sW2[j * 31 + m] * a[m];
            t[j] = s;
        }
        #pragma unroll
        for (int l = 0; l < 6; l++) {
            float u[10];
            #pragma unroll
            for (int j = 0; j < 10; j++) {
                float s = isBias ? sbs[l + 1][j] : 0.f;
                #pragma unroll
                for (int m = 0; m < 10; m++) s += sWs[l][j * 10 + m] * t[m];
                u[j] = s;
            }
            #pragma unroll
            for (int j = 0; j < 10; j++) t[j] = u[j];
        }
        if (!isBias) {
            #pragma unroll
            for (int j = 0; j < 10; j++) sP[j * 69 + tid] = t[j];
        } else {
            #pragma unroll
            for (int j = 0; j < 10; j++) sc[j] = t[j];
        }
    }
    __syncthreads();

    // M[j][i4*4..+3] = P[j,:] @ W0[:, i4*4..+3], then bf16 hi/lo split.
    int idx = blockIdx.x * 256 + tid;
    if (idx < 1960) {
        int j = idx / 196, i4 = idx % 196;
        const float4* W04 = reinterpret_cast<const float4*>(W0);
        float4 acc = make_float4(0.f, 0.f, 0.f, 0.f);
        #pragma unroll 23
        for (int k = 0; k < 69; k++) {
            float4 w = W04[k * 196 + i4];
            float p = sP[j * 69 + k];
            acc.x += p * w.x; acc.y += p * w.y;
            acc.z += p * w.z; acc.w += p * w.w;
        }
        __nv_bfloat162 h01 = __float22bfloat162_rn(make_float2(acc.x, acc.y));
        __nv_bfloat162 h23 = __float22bfloat162_rn(make_float2(acc.z, acc.w));
        float2 f01 = __bfloat1622float2(h01);
        float2 f23 = __bfloat1622float2(h23);
        __nv_bfloat162 l01 = __float22bfloat162_rn(make_float2(acc.x - f01.x, acc.y - f01.y));
        __nv_bfloat162 l23 = __float22bfloat162_rn(make_float2(acc.z - f23.x, acc.w - f23.y));
        uint2 hu, lu;
        hu.x = reinterpret_cast<unsigned&>(h01);
        hu.y = reinterpret_cast<unsigned&>(h23);
        lu.x = reinterpret_cast<unsigned&>(l01);
        lu.y = reinterpret_cast<unsigned&>(l23);
        reinterpret_cast<uint2*>(g_Bhi)[j * 198 + i4] = hu;   // (j*792 + i4*4) bf16
        reinterpret_cast<uint2*>(g_Blo)[j * 198 + i4] = lu;
    }

    // zero padding: rows 10..15 fully; cols 784..791 of rows 0..9
    if (blockIdx.x == 7) {
        unsigned* zh = reinterpret_cast<unsigned*>(g_Bhi + 10 * 792);
        unsigned* zl = reinterpret_cast<unsigned*>(g_Blo + 10 * 792);
        for (int e = tid; e < 6 * 792 / 2; e += 256) { zh[e] = 0u; zl[e] = 0u; }
        if (tid < 40) {
            int j = tid >> 2, w = tid & 3;
            reinterpret_cast<unsigned*>(g_Bhi + j * 792 + 784)[w] = 0u;
            reinterpret_cast<unsigned*>(g_Blo + j * 792 + 784)[w] = 0u;
        }
    }

    if (blockIdx.x == 0 && tid < 10) {
        float s = sc[tid];
        #pragma unroll 23
        for (int k = 0; k < 69; k++) s += sP[tid * 69 + k] * sb0[k];
        g_c[tid] = s;
    }
}

// ---------------------------------------------------------------------------
// HMMA GEMM, smem-free A path:
// A fragments are built DIRECTLY from global LDG.128 using an implicit k-
// permutation inside each 16-column block (consistent between A and B, so
// the mma result is exact): lane lq loads float4 at phys cols 16kb+4lq;
// (x,y) -> a0/a1 (logical k-lo pair), (z,w) -> a2/a3 (logical k-hi pair).
// Matching B words are then CONTIGUOUS: one LDS.64 per n-tile per half.
// No A smem, no loop barriers (single sync after B staging).
// Hi/lo error compensation: xh*Mh + xh*Ml + xl*Mh.
// Block = 256 threads (8 warps), warp = 16 rows, tile = 128 rows.
// ---------------------------------------------------------------------------
#define MMA16816(d0,d1,d2,d3,a0,a1,a2,a3,b0,b1) \
    asm volatile("mma.sync.aligned.m16n8k16.row.col.f32.bf16.bf16.f32 " \
        "{%0,%1,%2,%3}, {%4,%5,%6,%7}, {%8,%9}, {%0,%1,%2,%3};" \
        : "+f"(d0), "+f"(d1), "+f"(d2), "+f"(d3) \
        : "r"(a0), "r"(a1), "r"(a2), "r"(a3), "r"(b0), "r"(b1))

#define SM_TOTAL 50688   // B hi (25344) + B lo (25344)

__device__ __forceinline__ void split4(const float4& v, uint2& hu, uint2& lu) {
    __nv_bfloat162 h01 = __float22bfloat162_rn(make_float2(v.x, v.y));
    __nv_bfloat162 h23 = __float22bfloat162_rn(make_float2(v.z, v.w));
    float2 f01 = __bfloat1622float2(h01);
    float2 f23 = __bfloat1622float2(h23);
    __nv_bfloat162 l01 = __float22bfloat162_rn(make_float2(v.x - f01.x, v.y - f01.y));
    __nv_bfloat162 l23 = __float22bfloat162_rn(make_float2(v.z - f23.x, v.w - f23.y));
    hu.x = reinterpret_cast<unsigned&>(h01);
    hu.y = reinterpret_cast<unsigned&>(h23);
    lu.x = reinterpret_cast<unsigned&>(l01);
    lu.y = reinterpret_cast<unsigned&>(l23);
}

__global__ void __launch_bounds__(256) gemm_hmma(
    const float* __restrict__ x, float* __restrict__ y, int rows)
{
    extern __shared__ char smem[];
    __nv_bfloat16* sBhi = reinterpret_cast<__nv_bfloat16*>(smem);
    __nv_bfloat16* sBlo = reinterpret_cast<__nv_bfloat16*>(smem + 25344);

    const int tid = threadIdx.x;
    const int warp = tid >> 5;
    const int lane = tid & 31;
    const int r  = lane >> 2;   // 0..7 (row within half-tile AND B n-row)
    const int lq = lane & 3;    // k-quad

    // stage B (hi+lo) once
    {
        const float4* gh = reinterpret_cast<const float4*>(g_Bhi);
        const float4* gl = reinterpret_cast<const float4*>(g_Blo);
        float4* sh = reinterpret_cast<float4*>(sBhi);
        float4* sl = reinterpret_cast<float4*>(sBlo);
        for (int t = tid; t < 1584; t += 256) { sh[t] = gh[t]; sl[t] = gl[t]; }
    }
    __syncthreads();

    const long rowLo = (long)blockIdx.x * 128 + warp * 16 + r;
    const long rowHi = rowLo + 8;
    const bool okLo = rowLo < rows;
    const bool okHi = rowHi < rows;

    const float4* xLo = reinterpret_cast<const float4*>(x + (okLo ? rowLo : 0) * 784);
    const float4* xHi = reinterpret_cast<const float4*>(x + (okHi ? rowHi : 0) * 784);

    // B pointers: uint2 = 8B = 4 bf16; row stride = 198 uint2
    const uint2* BH = reinterpret_cast<const uint2*>(sBhi);
    const uint2* BL = reinterpret_cast<const uint2*>(sBlo);
    const int bn0 = r * 198 + lq;          // n = r      (ntile 0)
    const int bn1 = (r + 8) * 198 + lq;    // n = r + 8  (ntile 1)

    float c00 = 0.f, c01 = 0.f, c02 = 0.f, c03 = 0.f;
    float c10 = 0.f, c11 = 0.f, c12 = 0.f, c13 = 0.f;

    // ring-1 prefetch of A
    float4 vLo = xLo[lq];
    float4 vHi = xHi[lq];

    #pragma unroll 4
    for (int kb = 0; kb < 49; kb++) {
        float4 nLo, nHi;
        if (kb < 48) {
            nLo = xLo[(kb + 1) * 4 + lq];
            nHi = xHi[(kb + 1) * 4 + lq];
        }

        uint2 aLoH, aLoL, aHiH, aHiL;
        split4(vLo, aLoH, aLoL);
        split4(vHi, aHiH, aHiL);
        // fragments: a0 = aLoH.x (row r, k-lo), a1 = aHiH.x (row r+8, k-lo),
        //            a2 = aLoH.y (row r, k-hi), a3 = aHiH.y (row r+8, k-hi)

        const int bo = kb * 4;   // uint2 offset for this k-block
        uint2 bh0 = BH[bn0 + bo];
        uint2 bh1 = BH[bn1 + bo];
        uint2 bl0 = BL[bn0 + bo];
        uint2 bl1 = BL[bn1 + bo];

        MMA16816(c00, c01, c02, c03, aLoH.x, aHiH.x, aLoH.y, aHiH.y, bh0.x, bh0.y);
        MMA16816(c10, c11, c12, c13, aLoH.x, aHiH.x, aLoH.y, aHiH.y, bh1.x, bh1.y);
        MMA16816(c00, c01, c02, c03, aLoH.x, aHiH.x, aLoH.y, aHiH.y, bl0.x, bl0.y);
        MMA16816(c10, c11, c12, c13, aLoH.x, aHiH.x, aLoH.y, aHiH.y, bl1.x, bl1.y);
        MMA16816(c00, c01, c02, c03, aLoL.x, aHiL.x, aLoL.y, aHiL.y, bh0.x, bh0.y);
        MMA16816(c10, c11, c12, c13, aLoL.x, aHiL.x, aLoL.y, aHiL.y, bh1.x, bh1.y);

        vLo = nLo; vHi = nHi;
    }

    // ---- epilogue: D frag -> y, add bias ----
    // c00,c01 = (rowLo, 2lq, 2lq+1); c02,c03 = (rowHi, ...); ntile1: n = 8+2lq (lq==0 only)
    const float b0v = g_c[lq * 2];
    const float b1v = g_c[lq * 2 + 1];
    const float b8v = g_c[8];
    const float b9v = g_c[9];

    if (okLo) {
        reinterpret_cast<float2*>(y + rowLo * 10 + lq * 2)[0] =
            make_float2(c00 + b0v, c01 + b1v);
        if (lq == 0)
            reinterpret_cast<float2*>(y + rowLo * 10 + 8)[0] =
                make_float2(c10 + b8v, c11 + b9v);
    }
    if (okHi) {
        reinterpret_cast<float2*>(y + rowHi * 10 + lq * 2)[0] =
            make_float2(c02 + b0v, c03 + b1v);
        if (lq == 0)
            reinterpret_cast<float2*>(y + rowHi * 10 + 8)[0] =
                make_float2(c12 + b8v, c13 + b9v);
    }
}

// ---------------------------------------------------------------------------
extern "C" void kernel_launch(void* const* d_in, const int* in_sizes, int n_in,
                              void* d_out, int out_size)
{
    const float* x = (const float*)d_in[0];
    const float* W[9];
    const float* b[9];
    for (int l = 0; l < 9; l++) {
        W[l] = (const float*)d_in[1 + 2 * l];
        b[l] = (const float*)d_in[2 + 2 * l];
    }
    float* y = (float*)d_out;
    int rows = in_sizes[0] / 784;

    static bool attr_set = false;
    if (!attr_set) {
        cudaFuncSetAttribute(gemm_hmma,
                             cudaFuncAttributeMaxDynamicSharedMemorySize, SM_TOTAL);
        attr_set = true;
    }

    compose_kernel<<<8, 256>>>(
        W[0], b[0], W[1], b[1], W[2], b[2], W[3], b[3], W[4], b[4],
        W[5], b[5], W[6], b[6], W[7], b[7], W[8], b[8]);

    int blocks = (rows + 127) / 128;
    gemm_hmma<<<blocks, 256, SM_TOTAL>>>(x, y, rows);
}

// round 10
// speedup vs baseline: 1.5120x; 1.5120x over previous
#include <cuda_runtime.h>
#include <cuda_bf16.h>

// Composed chain outputs (written by compose_kernel):
//   g_Bhi/g_Blo: bf16 split of M^T laid out [16][792] (n-major, k-contiguous,
//                row stride 792 bf16; rows 10..15 and cols 784..791 zero)
//   g_c: folded bias [10]
__device__ __align__(16) __nv_bfloat16 g_Bhi[16 * 792];
__device__ __align__(16) __nv_bfloat16 g_Blo[16 * 792];
__device__ float g_c[10];

// ---------------------------------------------------------------------------
// Compose kernel (grid=8): P = W8*...*W1 via thread-local register chain
// (70 threads, no syncs), then M = P*W0 slice per block, split into bf16
// hi/lo and written into the padded B layout. Block 0 folds bias, block 7
// zeroes the padding regions.
// ---------------------------------------------------------------------------
__global__ void __launch_bounds__(256) compose_kernel(
    const float* __restrict__ W0, const float* __restrict__ b0,
    const float* __restrict__ W1, const float* __restrict__ b1,
    const float* __restrict__ W2, const float* __restrict__ b2,
    const float* __restrict__ W3, const float* __restrict__ b3,
    const float* __restrict__ W4, const float* __restrict__ b4,
    const float* __restrict__ W5, const float* __restrict__ b5,
    const float* __restrict__ W6, const float* __restrict__ b6,
    const float* __restrict__ W7, const float* __restrict__ b7,
    const float* __restrict__ W8, const float* __restrict__ b8)
{
    __shared__ float sW2[10 * 31];
    __shared__ float sWs[6][100];
    __shared__ float sb1[31];
    __shared__ float sbs[7][10];
    __shared__ float sb0[69];
    __shared__ float sP[10 * 69];
    __shared__ float sc[10];

    const int tid = threadIdx.x;

    for (int e = tid; e < 310; e += 256) sW2[e] = W2[e];
    if (tid < 100) {
        sWs[0][tid] = W3[tid]; sWs[1][tid] = W4[tid]; sWs[2][tid] = W5[tid];
        sWs[3][tid] = W6[tid]; sWs[4][tid] = W7[tid]; sWs[5][tid] = W8[tid];
    }
    if (tid < 31) sb1[tid] = b1[tid];
    if (tid < 69) sb0[tid] = b0[tid];
    if (tid < 10) {
        sbs[0][tid] = b2[tid]; sbs[1][tid] = b3[tid]; sbs[2][tid] = b4[tid];
        sbs[3][tid] = b5[tid]; sbs[4][tid] = b6[tid]; sbs[5][tid] = b7[tid];
        sbs[6][tid] = b8[tid];
    }
    __syncthreads();

    if (tid < 70) {
        const bool isBias = (tid == 69);
        float a[31];
        if (!isBias) {
            #pragma unroll
            for (int m = 0; m < 31; m++) a[m] = W1[m * 69 + tid];
        } else {
            #pragma unroll
            for (int m = 0; m < 31; m++) a[m] = sb1[m];
        }
        float t[10];
        #pragma unroll
        for (int j = 0; j < 10; j++) {
            float s = isBias ? sbs[0][j] : 0.f;
            #pragma unroll
            for (int m = 0; m < 31; m++) s += sW2[j * 31 + m] * a[m];
            t[j] = s;
        }
        #pragma unroll
        for (int l = 0; l < 6; l++) {
            float u[10];
            #pragma unroll
            for (int j = 0; j < 10; j++) {
                float s = isBias ? sbs[l + 1][j] : 0.f;
                #pragma unroll
                for (int m = 0; m < 10; m++) s += sWs[l][j * 10 + m] * t[m];
                u[j] = s;
            }
            #pragma unroll
            for (int j = 0; j < 10; j++) t[j] = u[j];
        }
        if (!isBias) {
            #pragma unroll
            for (int j = 0; j < 10; j++) sP[j * 69 + tid] = t[j];
        } else {
            #pragma unroll
            for (int j = 0; j < 10; j++) sc[j] = t[j];
        }
    }
    __syncthreads();

    // M[j][i4*4..+3] = P[j,:] @ W0[:, i4*4..+3], then bf16 hi/lo split.
    int idx = blockIdx.x * 256 + tid;
    if (idx < 1960) {
        int j = idx / 196, i4 = idx % 196;
        const float4* W04 = reinterpret_cast<const float4*>(W0);
        float4 acc = make_float4(0.f, 0.f, 0.f, 0.f);
        #pragma unroll 23
        for (int k = 0; k < 69; k++) {
            float4 w = W04[k * 196 + i4];
            float p = sP[j * 69 + k];
            acc.x += p * w.x; acc.y += p * w.y;
            acc.z += p * w.z; acc.w += p * w.w;
        }
        __nv_bfloat162 h01 = __float22bfloat162_rn(make_float2(acc.x, acc.y));
        __nv_bfloat162 h23 = __float22bfloat162_rn(make_float2(acc.z, acc.w));
        float2 f01 = __bfloat1622float2(h01);
        float2 f23 = __bfloat1622float2(h23);
        __nv_bfloat162 l01 = __float22bfloat162_rn(make_float2(acc.x - f01.x, acc.y - f01.y));
        __nv_bfloat162 l23 = __float22bfloat162_rn(make_float2(acc.z - f23.x, acc.w - f23.y));
        uint2 hu, lu;
        hu.x = reinterpret_cast<unsigned&>(h01);
        hu.y = reinterpret_cast<unsigned&>(h23);
        lu.x = reinterpret_cast<unsigned&>(l01);
        lu.y = reinterpret_cast<unsigned&>(l23);
        reinterpret_cast<uint2*>(g_Bhi)[j * 198 + i4] = hu;   // (j*792 + i4*4) bf16
        reinterpret_cast<uint2*>(g_Blo)[j * 198 + i4] = lu;
    }

    // zero padding: rows 10..15 fully; cols 784..791 of rows 0..9
    if (blockIdx.x == 7) {
        unsigned* zh = reinterpret_cast<unsigned*>(g_Bhi + 10 * 792);
        unsigned* zl = reinterpret_cast<unsigned*>(g_Blo + 10 * 792);
        for (int e = tid; e < 6 * 792 / 2; e += 256) { zh[e] = 0u; zl[e] = 0u; }
        if (tid < 40) {
            int j = tid >> 2, w = tid & 3;
            reinterpret_cast<unsigned*>(g_Bhi + j * 792 + 784)[w] = 0u;
            reinterpret_cast<unsigned*>(g_Blo + j * 792 + 784)[w] = 0u;
        }
    }

    if (blockIdx.x == 0 && tid < 10) {
        float s = sc[tid];
        #pragma unroll 23
        for (int k = 0; k < 69; k++) s += sP[tid * 69 + k] * sb0[k];
        g_c[tid] = s;
    }
}

// ---------------------------------------------------------------------------
// HMMA GEMM, smem-free A path with DEEP prefetch:
// A fragments built directly from global LDG.128 via the implicit in-block
// k-permutation (consistent for A and B, so result is exact). Ring-4
// prefetch keeps 8 LDG.128 (128B) in flight per thread to cover DRAM
// latency. Separate accumulator sets for hi*hi and correction terms keep
// MMA dependency chains <= 2 per iteration.
// Hi/lo error compensation: xh*Mh + (xh*Ml + xl*Mh).
// Block = 256 threads (8 warps), warp = 16 rows, tile = 128 rows.
// ---------------------------------------------------------------------------
#define MMA16816(d0,d1,d2,d3,a0,a1,a2,a3,b0,b1) \
    asm volatile("mma.sync.aligned.m16n8k16.row.col.f32.bf16.bf16.f32 " \
        "{%0,%1,%2,%3}, {%4,%5,%6,%7}, {%8,%9}, {%0,%1,%2,%3};" \
        : "+f"(d0), "+f"(d1), "+f"(d2), "+f"(d3) \
        : "r"(a0), "r"(a1), "r"(a2), "r"(a3), "r"(b0), "r"(b1))

#define SM_TOTAL 50688   // B hi (25344) + B lo (25344)

__device__ __forceinline__ void split4(const float4& v, uint2& hu, uint2& lu) {
    __nv_bfloat162 h01 = __float22bfloat162_rn(make_float2(v.x, v.y));
    __nv_bfloat162 h23 = __float22bfloat162_rn(make_float2(v.z, v.w));
    float2 f01 = __bfloat1622float2(h01);
    float2 f23 = __bfloat1622float2(h23);
    __nv_bfloat162 l01 = __float22bfloat162_rn(make_float2(v.x - f01.x, v.y - f01.y));
    __nv_bfloat162 l23 = __float22bfloat162_rn(make_float2(v.z - f23.x, v.w - f23.y));
    hu.x = reinterpret_cast<unsigned&>(h01);
    hu.y = reinterpret_cast<unsigned&>(h23);
    lu.x = reinterpret_cast<unsigned&>(l01);
    lu.y = reinterpret_cast<unsigned&>(l23);
}

__global__ void __launch_bounds__(256) gemm_hmma(
    const float* __restrict__ x, float* __restrict__ y, int rows)
{
    extern __shared__ char smem[];
    __nv_bfloat16* sBhi = reinterpret_cast<__nv_bfloat16*>(smem);
    __nv_bfloat16* sBlo = reinterpret_cast<__nv_bfloat16*>(smem + 25344);

    const int tid = threadIdx.x;
    const int warp = tid >> 5;
    const int lane = tid & 31;
    const int r  = lane >> 2;   // 0..7 (row within half-tile AND B n-row)
    const int lq = lane & 3;    // k-quad

    // stage B (hi+lo) once
    {
        const float4* gh = reinterpret_cast<const float4*>(g_Bhi);
        const float4* gl = reinterpret_cast<const float4*>(g_Blo);
        float4* sh = reinterpret_cast<float4*>(sBhi);
        float4* sl = reinterpret_cast<float4*>(sBlo);
        for (int t = tid; t < 1584; t += 256) { sh[t] = gh[t]; sl[t] = gl[t]; }
    }
    __syncthreads();

    const long rowLo = (long)blockIdx.x * 128 + warp * 16 + r;
    const long rowHi = rowLo + 8;
    const bool okLo = rowLo < rows;
    const bool okHi = rowHi < rows;

    const float4* xLo = reinterpret_cast<const float4*>(x + (okLo ? rowLo : 0) * 784);
    const float4* xHi = reinterpret_cast<const float4*>(x + (okHi ? rowHi : 0) * 784);

    // B pointers: uint2 = 8B = 4 bf16; row stride = 198 uint2
    const uint2* BH = reinterpret_cast<const uint2*>(sBhi);
    const uint2* BL = reinterpret_cast<const uint2*>(sBlo);
    const int bn0 = r * 198 + lq;          // n = r      (ntile 0)
    const int bn1 = (r + 8) * 198 + lq;    // n = r + 8  (ntile 1)

    // hi*hi accumulators and correction accumulators (independent chains)
    float cH00 = 0.f, cH01 = 0.f, cH02 = 0.f, cH03 = 0.f;
    float cH10 = 0.f, cH11 = 0.f, cH12 = 0.f, cH13 = 0.f;
    float cC00 = 0.f, cC01 = 0.f, cC02 = 0.f, cC03 = 0.f;
    float cC10 = 0.f, cC11 = 0.f, cC12 = 0.f, cC13 = 0.f;

    // ring-4 prefetch of A (8 LDG.128 in flight)
    float4 pfLo[4], pfHi[4];
    #pragma unroll
    for (int i = 0; i < 4; i++) {
        pfLo[i] = xLo[i * 4 + lq];
        pfHi[i] = xHi[i * 4 + lq];
    }

    #pragma unroll 4
    for (int kb = 0; kb < 49; kb++) {
        float4 vLo = pfLo[kb & 3];
        float4 vHi = pfHi[kb & 3];
        const int nk = kb + 4;
        if (nk < 49) {
            pfLo[kb & 3] = xLo[nk * 4 + lq];
            pfHi[kb & 3] = xHi[nk * 4 + lq];
        }

        uint2 aLoH, aLoL, aHiH, aHiL;
        split4(vLo, aLoH, aLoL);
        split4(vHi, aHiH, aHiL);
        // fragments: a0 = (row r, k-lo), a1 = (row r+8, k-lo),
        //            a2 = (row r, k-hi), a3 = (row r+8, k-hi)

        const int bo = kb * 4;   // uint2 offset for this k-block
        uint2 bh0 = BH[bn0 + bo];
        uint2 bh1 = BH[bn1 + bo];
        uint2 bl0 = BL[bn0 + bo];
        uint2 bl1 = BL[bn1 + bo];

        // hi*hi -> cH (1 MMA per acc set per iter)
        MMA16816(cH00, cH01, cH02, cH03, aLoH.x, aHiH.x, aLoH.y, aHiH.y, bh0.x, bh0.y);
        MMA16816(cH10, cH11, cH12, cH13, aLoH.x, aHiH.x, aLoH.y, aHiH.y, bh1.x, bh1.y);
        // corrections -> cC (2 MMA chain per acc set per iter)
        MMA16816(cC00, cC01, cC02, cC03, aLoH.x, aHiH.x, aLoH.y, aHiH.y, bl0.x, bl0.y);
        MMA16816(cC10, cC11, cC12, cC13, aLoH.x, aHiH.x, aLoH.y, aHiH.y, bl1.x, bl1.y);
        MMA16816(cC00, cC01, cC02, cC03, aLoL.x, aHiL.x, aLoL.y, aHiL.y, bh0.x, bh0.y);
        MMA16816(cC10, cC11, cC12, cC13, aLoL.x, aHiL.x, aLoL.y, aHiL.y, bh1.x, bh1.y);
    }

    // ---- epilogue: merge acc sets, add bias, store ----
    const float b0v = g_c[lq * 2];
    const float b1v = g_c[lq * 2 + 1];
    const float b8v = g_c[8];
    const float b9v = g_c[9];

    if (okLo) {
        reinterpret_cast<float2*>(y + rowLo * 10 + lq * 2)[0] =
            make_float2(cH00 + cC00 + b0v, cH01 + cC01 + b1v);
        if (lq == 0)
            reinterpret_cast<float2*>(y + rowLo * 10 + 8)[0] =
                make_float2(cH10 + cC10 + b8v, cH11 + cC11 + b9v);
    }
    if (okHi) {
        reinterpret_cast<float2*>(y + rowHi * 10 + lq * 2)[0] =
            make_float2(cH02 + cC02 + b0v, cH03 + cC03 + b1v);
        if (lq == 0)
            reinterpret_cast<float2*>(y + rowHi * 10 + 8)[0] =
                make_float2(cH12 + cC12 + b8v, cH13 + cC13 + b9v);
    }
}

// ---------------------------------------------------------------------------
extern "C" void kernel_launch(void* const* d_in, const int* in_sizes, int n_in,
                              void* d_out, int out_size)
{
    const float* x = (const float*)d_in[0];
    const float* W[9];
    const float* b[9];
    for (int l = 0; l < 9; l++) {
        W[l] = (const float*)d_in[1 + 2 * l];
        b[l] = (const float*)d_in[2 + 2 * l];
    }
    float* y = (float*)d_out;
    int rows = in_sizes[0] / 784;

    static bool attr_set = false;
    if (!attr_set) {
        cudaFuncSetAttribute(gemm_hmma,
                             cudaFuncAttributeMaxDynamicSharedMemorySize, SM_TOTAL);
        attr_set = true;
    }

    compose_kernel<<<8, 256>>>(
        W[0], b[0], W[1], b[1], W[2], b[2], W[3], b[3], W[4], b[4],
        W[5], b[5], W[6], b[6], W[7], b[7], W[8], b[8]);

    int blocks = (rows + 127) / 128;
    gemm_hmma<<<blocks, 256, SM_TOTAL>>>(x, y, rows);
}

// round 11
// speedup vs baseline: 1.7568x; 1.1619x over previous
#include <cuda_runtime.h>
#include <cuda_bf16.h>

// Composed chain outputs (written by compose_kernel):
//   g_Bhi/g_Blo: bf16 split of M^T laid out [16][792] (n-major, k-contiguous,
//                row stride 792 bf16; rows 10..15 and cols 784..791 zero)
//   g_c: folded bias [10]
__device__ __align__(16) __nv_bfloat16 g_Bhi[16 * 792];
__device__ __align__(16) __nv_bfloat16 g_Blo[16 * 792];
__device__ float g_c[10];

// ---------------------------------------------------------------------------
// Compose kernel (grid=8): P = W8*...*W1 via thread-local register chain
// (70 threads, no syncs), then M = P*W0 slice per block, split into bf16
// hi/lo and written into the padded B layout. Block 0 folds bias, block 7
// zeroes the padding regions.
// ---------------------------------------------------------------------------
__global__ void __launch_bounds__(256) compose_kernel(
    const float* __restrict__ W0, const float* __restrict__ b0,
    const float* __restrict__ W1, const float* __restrict__ b1,
    const float* __restrict__ W2, const float* __restrict__ b2,
    const float* __restrict__ W3, const float* __restrict__ b3,
    const float* __restrict__ W4, const float* __restrict__ b4,
    const float* __restrict__ W5, const float* __restrict__ b5,
    const float* __restrict__ W6, const float* __restrict__ b6,
    const float* __restrict__ W7, const float* __restrict__ b7,
    const float* __restrict__ W8, const float* __restrict__ b8)
{
    __shared__ float sW2[10 * 31];
    __shared__ float sWs[6][100];
    __shared__ float sb1[31];
    __shared__ float sbs[7][10];
    __shared__ float sb0[69];
    __shared__ float sP[10 * 69];
    __shared__ float sc[10];

    const int tid = threadIdx.x;

    for (int e = tid; e < 310; e += 256) sW2[e] = W2[e];
    if (tid < 100) {
        sWs[0][tid] = W3[tid]; sWs[1][tid] = W4[tid]; sWs[2][tid] = W5[tid];
        sWs[3][tid] = W6[tid]; sWs[4][tid] = W7[tid]; sWs[5][tid] = W8[tid];
    }
    if (tid < 31) sb1[tid] = b1[tid];
    if (tid < 69) sb0[tid] = b0[tid];
    if (tid < 10) {
        sbs[0][tid] = b2[tid]; sbs[1][tid] = b3[tid]; sbs[2][tid] = b4[tid];
        sbs[3][tid] = b5[tid]; sbs[4][tid] = b6[tid]; sbs[5][tid] = b7[tid];
        sbs[6][tid] = b8[tid];
    }
    __syncthreads();

    if (tid < 70) {
        const bool isBias = (tid == 69);
        float a[31];
        if (!isBias) {
            #pragma unroll
            for (int m = 0; m < 31; m++) a[m] = W1[m * 69 + tid];
        } else {
            #pragma unroll
            for (int m = 0; m < 31; m++) a[m] = sb1[m];
        }
        float t[10];
        #pragma unroll
        for (int j = 0; j < 10; j++) {
            float s = isBias ? sbs[0][j] : 0.f;
            #pragma unroll
            for (int m = 0; m < 31; m++) s += sW2[j * 31 + m] * a[m];
            t[j] = s;
        }
        #pragma unroll
        for (int l = 0; l < 6; l++) {
            float u[10];
            #pragma unroll
            for (int j = 0; j < 10; j++) {
                float s = isBias ? sbs[l + 1][j] : 0.f;
                #pragma unroll
                for (int m = 0; m < 10; m++) s += sWs[l][j * 10 + m] * t[m];
                u[j] = s;
            }
            #pragma unroll
            for (int j = 0; j < 10; j++) t[j] = u[j];
        }
        if (!isBias) {
            #pragma unroll
            for (int j = 0; j < 10; j++) sP[j * 69 + tid] = t[j];
        } else {
            #pragma unroll
            for (int j = 0; j < 10; j++) sc[j] = t[j];
        }
    }
    __syncthreads();

    // M[j][i4*4..+3] = P[j,:] @ W0[:, i4*4..+3], then bf16 hi/lo split.
    int idx = blockIdx.x * 256 + tid;
    if (idx < 1960) {
        int j = idx / 196, i4 = idx % 196;
        const float4* W04 = reinterpret_cast<const float4*>(W0);
        float4 acc = make_float4(0.f, 0.f, 0.f, 0.f);
        #pragma unroll 23
        for (int k = 0; k < 69; k++) {
            float4 w = W04[k * 196 + i4];
            float p = sP[j * 69 + k];
            acc.x += p * w.x; acc.y += p * w.y;
            acc.z += p * w.z; acc.w += p * w.w;
        }
        __nv_bfloat162 h01 = __float22bfloat162_rn(make_float2(acc.x, acc.y));
        __nv_bfloat162 h23 = __float22bfloat162_rn(make_float2(acc.z, acc.w));
        float2 f01 = __bfloat1622float2(h01);
        float2 f23 = __bfloat1622float2(h23);
        __nv_bfloat162 l01 = __float22bfloat162_rn(make_float2(acc.x - f01.x, acc.y - f01.y));
        __nv_bfloat162 l23 = __float22bfloat162_rn(make_float2(acc.z - f23.x, acc.w - f23.y));
        uint2 hu, lu;
        hu.x = reinterpret_cast<unsigned&>(h01);
        hu.y = reinterpret_cast<unsigned&>(h23);
        lu.x = reinterpret_cast<unsigned&>(l01);
        lu.y = reinterpret_cast<unsigned&>(l23);
        reinterpret_cast<uint2*>(g_Bhi)[j * 198 + i4] = hu;   // (j*792 + i4*4) bf16
        reinterpret_cast<uint2*>(g_Blo)[j * 198 + i4] = lu;
    }

    // zero padding: rows 10..15 fully; cols 784..791 of rows 0..9
    if (blockIdx.x == 7) {
        unsigned* zh = reinterpret_cast<unsigned*>(g_Bhi + 10 * 792);
        unsigned* zl = reinterpret_cast<unsigned*>(g_Blo + 10 * 792);
        for (int e = tid; e < 6 * 792 / 2; e += 256) { zh[e] = 0u; zl[e] = 0u; }
        if (tid < 40) {
            int j = tid >> 2, w = tid & 3;
            reinterpret_cast<unsigned*>(g_Bhi + j * 792 + 784)[w] = 0u;
            reinterpret_cast<unsigned*>(g_Blo + j * 792 + 784)[w] = 0u;
        }
    }

    if (blockIdx.x == 0 && tid < 10) {
        float s = sc[tid];
        #pragma unroll 23
        for (int k = 0; k < 69; k++) s += sP[tid * 69 + k] * sb0[k];
        g_c[tid] = s;
    }
}

// ---------------------------------------------------------------------------
// HMMA GEMM with warp-autonomous cp.async pipeline:
// Each warp owns 16 rows. A 6-stage per-warp smem ring is filled with raw
// fp32 x tiles via cp.async.cg (no register scoreboard involvement); the
// consumer waits on cp.async.wait_group 4 (5 stages in flight cover DRAM
// latency), reads A via LDS.128, converts to bf16 hi/lo in registers, and
// feeds mma.sync with the implicit in-block k-permutation (consistent for
// A and B, so the result is exact). No block barriers in the main loop.
// Hi/lo error compensation: xh*Mh + (xh*Ml + xl*Mh).
// Block = 256 threads (8 warps), warp = 16 rows, tile = 128 rows.
// ---------------------------------------------------------------------------
#define MMA16816(d0,d1,d2,d3,a0,a1,a2,a3,b0,b1) \
    asm volatile("mma.sync.aligned.m16n8k16.row.col.f32.bf16.bf16.f32 " \
        "{%0,%1,%2,%3}, {%4,%5,%6,%7}, {%8,%9}, {%0,%1,%2,%3};" \
        : "+f"(d0), "+f"(d1), "+f"(d2), "+f"(d3) \
        : "r"(a0), "r"(a1), "r"(a2), "r"(a3), "r"(b0), "r"(b1))

#define SM_A     50688                 // after B hi (25344) + B lo (25344)
#define SM_TOTAL (50688 + 8 * 6 * 1024)  // + 8 warps * 6 stages * 1KB = 99840

__device__ __forceinline__ void cpasync16(unsigned dst, const void* src) {
    asm volatile("cp.async.cg.shared.global [%0], [%1], 16;"
                 :: "r"(dst), "l"(src));
}
__device__ __forceinline__ void cpcommit() {
    asm volatile("cp.async.commit_group;" ::: "memory");
}

__device__ __forceinline__ void split4(const float4& v, uint2& hu, uint2& lu) {
    __nv_bfloat162 h01 = __float22bfloat162_rn(make_float2(v.x, v.y));
    __nv_bfloat162 h23 = __float22bfloat162_rn(make_float2(v.z, v.w));
    float2 f01 = __bfloat1622float2(h01);
    float2 f23 = __bfloat1622float2(h23);
    __nv_bfloat162 l01 = __float22bfloat162_rn(make_float2(v.x - f01.x, v.y - f01.y));
    __nv_bfloat162 l23 = __float22bfloat162_rn(make_float2(v.z - f23.x, v.w - f23.y));
    hu.x = reinterpret_cast<unsigned&>(h01);
    hu.y = reinterpret_cast<unsigned&>(h23);
    lu.x = reinterpret_cast<unsigned&>(l01);
    lu.y = reinterpret_cast<unsigned&>(l23);
}

__global__ void __launch_bounds__(256) gemm_hmma(
    const float* __restrict__ x, float* __restrict__ y, int rows)
{
    extern __shared__ char smem[];
    __nv_bfloat16* sBhi = reinterpret_cast<__nv_bfloat16*>(smem);
    __nv_bfloat16* sBlo = reinterpret_cast<__nv_bfloat16*>(smem + 25344);

    const int tid  = threadIdx.x;
    const int warp = tid >> 5;
    const int lane = tid & 31;
    const int r  = lane >> 2;   // 0..7 (mma row within half-tile AND B n-row)
    const int lq = lane & 3;    // k-quad

    // ---- A pipeline setup (each warp loads the 16 rows it consumes) ----
    // f = lane*2 + i  ->  row-in-warp = lane>>1, float4-col = (lane&1)*2 + i
    const int  roww = lane >> 1;
    const int  c0   = (lane & 1) * 2;
    const long growA = (long)blockIdx.x * 128 + warp * 16 + roww;
    const float* xA = x + (growA < rows ? growA : 0) * 784 + c0 * 4;
    const unsigned aBase =
        (unsigned)__cvta_generic_to_shared(smem + SM_A + warp * 6144) + lane * 32;

    // prologue: stages 0..4 (5 groups in flight)
    #pragma unroll
    for (int s = 0; s < 5; s++) {
        cpasync16(aBase + s * 1024,      xA + s * 16);
        cpasync16(aBase + s * 1024 + 16, xA + s * 16 + 4);
        cpcommit();
    }

    // ---- stage B (hi+lo) once ----
    {
        const float4* gh = reinterpret_cast<const float4*>(g_Bhi);
        const float4* gl = reinterpret_cast<const float4*>(g_Blo);
        float4* sh = reinterpret_cast<float4*>(sBhi);
        float4* sl = reinterpret_cast<float4*>(sBlo);
        for (int t = tid; t < 1584; t += 256) { sh[t] = gh[t]; sl[t] = gl[t]; }
    }
    __syncthreads();

    const long rowLo = (long)blockIdx.x * 128 + warp * 16 + r;
    const long rowHi = rowLo + 8;
    const bool okLo = rowLo < rows;
    const bool okHi = rowHi < rows;

    // B pointers: uint2 = 8B = 4 bf16; row stride = 198 uint2
    const uint2* BH = reinterpret_cast<const uint2*>(sBhi);
    const uint2* BL = reinterpret_cast<const uint2*>(sBlo);
    const int bn0 = r * 198 + lq;          // n = r      (ntile 0)
    const int bn1 = (r + 8) * 198 + lq;    // n = r + 8  (ntile 1)

    // A read offsets within a stage
    const char* aRd = smem + SM_A + warp * 6144;
    const int aLoOff = (r * 4 + lq) * 16;
    const int aHiOff = ((r + 8) * 4 + lq) * 16;

    // hi*hi accumulators and correction accumulators (independent chains)
    float cH00 = 0.f, cH01 = 0.f, cH02 = 0.f, cH03 = 0.f;
    float cH10 = 0.f, cH11 = 0.f, cH12 = 0.f, cH13 = 0.f;
    float cC00 = 0.f, cC01 = 0.f, cC02 = 0.f, cC03 = 0.f;
    float cC10 = 0.f, cC11 = 0.f, cC12 = 0.f, cC13 = 0.f;

    int stageOff = 0;
    #pragma unroll 2
    for (int kb = 0; kb < 49; kb++) {
        // oldest stage (slot kb%6) is complete once <=4 groups remain pending
        asm volatile("cp.async.wait_group 4;" ::: "memory");
        __syncwarp();

        float4 vLo = *reinterpret_cast<const float4*>(aRd + stageOff + aLoOff);
        float4 vHi = *reinterpret_cast<const float4*>(aRd + stageOff + aHiOff);

        // refill slot (kb+5)%6 for k-block kb+5
        const int nk = kb + 5;
        if (nk < 49) {
            int nOff = stageOff + 5 * 1024;
            if (nOff >= 6144) nOff -= 6144;
            cpasync16(aBase + nOff,      xA + nk * 16);
            cpasync16(aBase + nOff + 16, xA + nk * 16 + 4);
        }
        cpcommit();   // one group per iteration keeps the count aligned

        uint2 aLoH, aLoL, aHiH, aHiL;
        split4(vLo, aLoH, aLoL);
        split4(vHi, aHiH, aHiL);

        const int bo = kb * 4;
        uint2 bh0 = BH[bn0 + bo];
        uint2 bh1 = BH[bn1 + bo];
        uint2 bl0 = BL[bn0 + bo];
        uint2 bl1 = BL[bn1 + bo];

        MMA16816(cH00, cH01, cH02, cH03, aLoH.x, aHiH.x, aLoH.y, aHiH.y, bh0.x, bh0.y);
        MMA16816(cH10, cH11, cH12, cH13, aLoH.x, aHiH.x, aLoH.y, aHiH.y, bh1.x, bh1.y);
        MMA16816(cC00, cC01, cC02, cC03, aLoH.x, aHiH.x, aLoH.y, aHiH.y, bl0.x, bl0.y);
        MMA16816(cC10, cC11, cC12, cC13, aLoH.x, aHiH.x, aLoH.y, aHiH.y, bl1.x, bl1.y);
        MMA16816(cC00, cC01, cC02, cC03, aLoL.x, aHiL.x, aLoL.y, aHiL.y, bh0.x, bh0.y);
        MMA16816(cC10, cC11, cC12, cC13, aLoL.x, aHiL.x, aLoL.y, aHiL.y, bh1.x, bh1.y);

        stageOff += 1024;
        if (stageOff == 6144) stageOff = 0;
    }

    // ---- epilogue: merge acc sets, add bias, store ----
    const float b0v = g_c[lq * 2];
    const float b1v = g_c[lq * 2 + 1];
    const float b8v = g_c[8];
    const float b9v = g_c[9];

    if (okLo) {
        reinterpret_cast<float2*>(y + rowLo * 10 + lq * 2)[0] =
            make_float2(cH00 + cC00 + b0v, cH01 + cC01 + b1v);
        if (lq == 0)
            reinterpret_cast<float2*>(y + rowLo * 10 + 8)[0] =
                make_float2(cH10 + cC10 + b8v, cH11 + cC11 + b9v);
    }
    if (okHi) {
        reinterpret_cast<float2*>(y + rowHi * 10 + lq * 2)[0] =
            make_float2(cH02 + cC02 + b0v, cH03 + cC03 + b1v);
        if (lq == 0)
            reinterpret_cast<float2*>(y + rowHi * 10 + 8)[0] =
                make_float2(cH12 + cC12 + b8v, cH13 + cC13 + b9v);
    }
}

// ---------------------------------------------------------------------------
extern "C" void kernel_launch(void* const* d_in, const int* in_sizes, int n_in,
                              void* d_out, int out_size)
{
    const float* x = (const float*)d_in[0];
    const float* W[9];
    const float* b[9];
    for (int l = 0; l < 9; l++) {
        W[l] = (const float*)d_in[1 + 2 * l];
        b[l] = (const float*)d_in[2 + 2 * l];
    }
    float* y = (float*)d_out;
    int rows = in_sizes[0] / 784;

    static bool attr_set = false;
    if (!attr_set) {
        cudaFuncSetAttribute(gemm_hmma,
                             cudaFuncAttributeMaxDynamicSharedMemorySize, SM_TOTAL);
        attr_set = true;
    }

    compose_kernel<<<8, 256>>>(
        W[0], b[0], W[1], b[1], W[2], b[2], W[3], b[3], W[4], b[4],
        W[5], b[5], W[6], b[6], W[7], b[7], W[8], b[8]);

    int blocks = (rows + 127) / 128;
    gemm_hmma<<<blocks, 256, SM_TOTAL>>>(x, y, rows);
}